// round 4
// baseline (speedup 1.0000x reference)
#include <cuda_runtime.h>

#define NB 32
#define NA 3
#define NH 52
#define NW 52
#define NC 80
#define CELLS_PER_B (NA*NH*NW)        // 8112
#define MAXB 50
#define BLK 256
#define GX ((CELLS_PER_B + BLK - 1)/BLK)  // 32
#define NPART (GX*NB)                 // 1024

__constant__ float c_AW[3] = {10.f/32.f, 16.f/32.f, 33.f/32.f};
__constant__ float c_AH[3] = {13.f/32.f, 30.f/32.f, 23.f/32.f};

// per-gt data, 4 float4s per gt slot:
//  [0] {x1, x2, y1, y2}              pred-overlap box corners
//  [1] {gw, gh, garea, cell-as-int}  sizes + target cell index
//  [2] {tx, ty, tw, th}              coord targets
//  [3] {scale, cls-as-int, 0, 0}
__device__ float4 g_gt[NB][MAXB][4];
__device__ int    g_nvalid[NB];
__device__ float  g_partial[NPART][3];

// ---------------- build per-gt targets (fully parallel) ----------------
__global__ void __launch_bounds__(64) kA(const float* __restrict__ target) {
    int b = blockIdx.x, t = threadIdx.x;
    __shared__ unsigned char s_ok[64];
    bool ok = false;
    if (t < MAXB) {
        const float* tp = target + b*MAXB*5 + t*5;
        float cc = tp[0], x = tp[1], y = tp[2], w = tp[3], h = tp[4];
        ok = (x != 0.f);
        float gx = x*(float)NW, gy = y*(float)NH, gw = w*(float)NW, gh = h*(float)NH;
        // best anchor vs (0,0,gw,gh), reference cxcywh IoU
        int bn = 0; float best = -1e30f;
#pragma unroll
        for (int a = 0; a < 3; a++) {
            float aw = c_AW[a], ah = c_AH[a];
            float Mx = fmaxf(0.5f*gw, 0.5f*aw) - fminf(-0.5f*gw, -0.5f*aw);
            float My = fmaxf(0.5f*gh, 0.5f*ah) - fminf(-0.5f*gh, -0.5f*ah);
            float cw = gw + aw - Mx;
            float ch = gh + ah - My;
            float ca = (cw <= 0.f || ch <= 0.f) ? 0.f : cw*ch;
            float iou = ca / (gw*gh + aw*ah - ca);
            if (iou > best) { best = iou; bn = a; }
        }
        int gi = (int)floorf(gx), gj = (int)floorf(gy);
        int cell = bn*(NH*NW) + gj*NW + gi;
        int cc_i = (int)cc; if (cc_i < 0) cc_i = 0; if (cc_i > NC-1) cc_i = NC-1;
        g_gt[b][t][0] = make_float4(gx - 0.5f*gw, gx + 0.5f*gw, gy - 0.5f*gh, gy + 0.5f*gh);
        g_gt[b][t][1] = make_float4(gw, gh, gw*gh, __int_as_float(cell));
        g_gt[b][t][2] = make_float4(gx - (float)gi, gy - (float)gj,
                                    logf(gw / c_AW[bn]), logf(gh / c_AH[bn]));
        g_gt[b][t][3] = make_float4(sqrtf(2.f - w*h), __int_as_float(cc_i), 0.f, 0.f);
    }
    // validity prefix: torch loop breaks at first slot with x==0
    s_ok[t] = ok ? 1 : 0;
    __syncthreads();
    if (t == 0) {
        int nv = 0;
        while (nv < MAXB && s_ok[nv]) nv++;
        g_nvalid[b] = nv;
    }
}

// ---------------- fused per-cell loss ----------------
__global__ void __launch_bounds__(BLK) kB(const float* __restrict__ out) {
    __shared__ float4 sg[MAXB][4];
    __shared__ int    s_nv;
    __shared__ float  s_red[3][BLK/32];

    int b = blockIdx.y, tid = threadIdx.x;
    if (tid == 0) s_nv = g_nvalid[b];
    if (tid < MAXB*4) ((float4*)sg)[tid] = ((const float4*)&g_gt[b][0][0])[tid];
    __syncthreads();

    int idx = blockIdx.x*BLK + tid;
    float coordL = 0.f, confL = 0.f, clsL = 0.f;

    if (idx < CELLS_PER_B) {
        int a  = idx / (NH*NW);
        int hw = idx - a*(NH*NW);
        int h  = hw / NW;
        int w  = hw - h*NW;
        const float* o = out + (size_t)(b*255 + a*85)*(NH*NW) + hw;
        float c0 = o[0];
        float c1 = o[1*(NH*NW)];
        float c2 = o[2*(NH*NW)];
        float c3 = o[3*(NH*NW)];
        float c4 = o[4*(NH*NW)];
        float s0 = 1.f/(1.f + expf(-c0));
        float s1 = 1.f/(1.f + expf(-c1));
        int aq = (b*3 + a) >> 5;                       // faithful anchor-flatten quirk
        float pw = expf(c2)*c_AW[aq], ph = expf(c3)*c_AH[aq];
        float px = s0 + (float)w,  py = s1 + (float)h;
        float px1 = px - 0.5f*pw, px2 = px + 0.5f*pw;
        float py1 = py - 0.5f*ph, py2 = py + 0.5f*ph;
        float parea = pw*ph;

        bool ign = false;
        int lastMatch = -1;
        unsigned cb0 = 0u, cb1 = 0u, cb2 = 0u;
        int nv = s_nv;
#pragma unroll 2
        for (int t2 = 0; t2 < nv; t2++) {
            float4 gA = sg[t2][0], gB = sg[t2][1];
            float cw  = (pw + gB.x) - (fmaxf(px2, gA.y) - fminf(px1, gA.x));
            float ch2 = (ph + gB.y) - (fmaxf(py2, gA.w) - fminf(py1, gA.z));
            // iou > 0.5  <=>  3*ca > parea + garea  (division-free)
            if (cw > 0.f && ch2 > 0.f && 3.f*(cw*ch2) > parea + gB.z) ign = true;
            if (__float_as_int(gB.w) == idx) {         // this gt targets my cell
                lastMatch = t2;
                int c = __float_as_int(sg[t2][3].y);
                if (c < 32)      cb0 |= 1u << c;
                else if (c < 64) cb1 |= 1u << (c - 32);
                else             cb2 |= 1u << (c - 64);
            }
        }

        float conf = 1.f/(1.f + expf(-c4));
        if (lastMatch >= 0) {
            confL = -fmaxf(logf(fmaxf(conf, 1e-38f)), -100.f);
            float4 tc = sg[lastMatch][2];
            float m  = sg[lastMatch][3].x;
            float d0 = s0*m - tc.x*m;
            float d1 = s1*m - tc.y*m;
            float d2 = c2*m - tc.z*m;
            float d3 = c3*m - tc.w*m;
            coordL = 0.5f*(d0*d0 + d1*d1 + d2*d2 + d3*d3);
#pragma unroll 4
            for (int c = 0; c < NC; c++) {
                float xv = o[(5 + c)*(NH*NW)];
                float p  = 1.f/(1.f + expf(-xv));
                unsigned bit = ((c < 32) ? (cb0 >> c) : (c < 64) ? (cb1 >> (c-32)) : (cb2 >> (c-64))) & 1u;
                float lg = bit ? logf(fmaxf(p, 1e-38f)) : logf(fmaxf(1.f - p, 1e-38f));
                clsL -= fmaxf(lg, -100.f);
            }
        } else if (!ign) {
            confL = -fmaxf(logf(fmaxf(1.f - conf, 1e-38f)), -100.f);
        }
    }

    // block reduce 3 sums
    unsigned fm = 0xffffffffu;
#pragma unroll
    for (int off = 16; off; off >>= 1) {
        coordL += __shfl_down_sync(fm, coordL, off);
        confL  += __shfl_down_sync(fm, confL,  off);
        clsL   += __shfl_down_sync(fm, clsL,   off);
    }
    int lane = tid & 31, wrp = tid >> 5;
    if (lane == 0) { s_red[0][wrp] = coordL; s_red[1][wrp] = confL; s_red[2][wrp] = clsL; }
    __syncthreads();
    if (tid < 3) {
        float s = 0.f;
#pragma unroll
        for (int j = 0; j < BLK/32; j++) s += s_red[tid][j];
        g_partial[blockIdx.y*gridDim.x + blockIdx.x][tid] = s;
    }
}

// ---------------- deterministic final reduce ----------------
__global__ void __launch_bounds__(256) kC(float* __restrict__ dout) {
    __shared__ float s_red[3][8];
    float a0 = 0.f, a1 = 0.f, a2 = 0.f;
    for (int i = threadIdx.x; i < NPART; i += 256) {
        a0 += g_partial[i][0]; a1 += g_partial[i][1]; a2 += g_partial[i][2];
    }
    unsigned fm = 0xffffffffu;
#pragma unroll
    for (int off = 16; off; off >>= 1) {
        a0 += __shfl_down_sync(fm, a0, off);
        a1 += __shfl_down_sync(fm, a1, off);
        a2 += __shfl_down_sync(fm, a2, off);
    }
    int lane = threadIdx.x & 31, wrp = threadIdx.x >> 5;
    if (lane == 0) { s_red[0][wrp] = a0; s_red[1][wrp] = a1; s_red[2][wrp] = a2; }
    __syncthreads();
    if (threadIdx.x < 3) {
        float s = 0.f;
#pragma unroll
        for (int j = 0; j < 8; j++) s += s_red[threadIdx.x][j];
        dout[threadIdx.x] = s / (float)NB;
    }
}

extern "C" void kernel_launch(void* const* d_in, const int* in_sizes, int n_in,
                              void* d_out, int out_size) {
    const float* output = (const float*)d_in[0];
    const float* target = (const float*)d_in[1];
    if (n_in >= 2 && in_sizes[0] == NB*MAXB*5) {  // defensive: inputs swapped
        output = (const float*)d_in[1];
        target = (const float*)d_in[0];
    }
    kA<<<NB, 64>>>(target);
    dim3 g(GX, NB);
    kB<<<g, BLK>>>(output);
    kC<<<1, 256>>>((float*)d_out);
}

// round 5
// speedup vs baseline: 1.4308x; 1.4308x over previous
#include <cuda_runtime.h>

#define NB 32
#define NA 3
#define NH 52
#define NW 52
#define NC 80
#define HW (NH*NW)                    // 2704
#define CELLS_PER_B (NA*HW)           // 8112
#define MAXB 50
#define BLK 256
#define CPT 2
#define CPB (BLK*CPT)                 // 512
#define GXB ((CELLS_PER_B + CPB - 1)/CPB)  // 16
#define NPART (GXB*NB)                // 512

__constant__ float c_AW[3] = {10.f/32.f, 16.f/32.f, 33.f/32.f};
__constant__ float c_AH[3] = {13.f/32.f, 30.f/32.f, 23.f/32.f};

__device__ float g_partial[NPART][3];

// ---------------- fused gt-build + per-cell loss ----------------
__global__ void __launch_bounds__(BLK) kB(const float* __restrict__ out,
                                          const float* __restrict__ target) {
    __shared__ float4   sA[MAXB];   // {x1, x2, y1, y2} gt corners
    __shared__ float2   sB[MAXB];   // {garea, cell-as-int}
    __shared__ float4   sC[MAXB];   // {tx, ty, tw, th}
    __shared__ float2   sD[MAXB];   // {scale, cls-as-int}
    __shared__ unsigned s_bal[2];
    __shared__ float    s_red[3][BLK/32];

    int b = blockIdx.y, tid = threadIdx.x;

    // ---- build gt table in shared (threads 0..49; ballot prefix over 2 warps) ----
    bool  ok = false;
    float cc = 0.f, x = 0.f, y = 0.f, w = 0.f, h = 0.f;
    if (tid < MAXB) {
        const float* tp = target + b*MAXB*5 + tid*5;
        cc = tp[0]; x = tp[1]; y = tp[2]; w = tp[3]; h = tp[4];
        ok = (x != 0.f);
    }
    if (tid < 64) {
        unsigned bal = __ballot_sync(0xffffffffu, ok);
        if ((tid & 31) == 0) s_bal[tid >> 5] = bal;
    }
    __syncthreads();
    if (tid < MAXB) {
        bool valid;
        if (tid < 32) {
            unsigned low = (tid == 31) ? 0xffffffffu : ((1u << (tid + 1)) - 1u);
            valid = ((s_bal[0] & low) == low);
        } else {
            unsigned low = (1u << (tid - 31)) - 1u;   // bits 0..(tid-32)
            valid = (s_bal[0] == 0xffffffffu) && ((s_bal[1] & low) == low);
        }
        if (valid) {
            float gx = x*(float)NW, gy = y*(float)NH;
            float gw = w*(float)NW, gh = h*(float)NH;
            // best anchor vs (0,0,gw,gh), reference cxcywh IoU (cold path: IEEE div)
            int bn = 0; float best = -1e30f;
#pragma unroll
            for (int a = 0; a < 3; a++) {
                float aw = c_AW[a], ah = c_AH[a];
                float cw = fminf(0.5f*gw, 0.5f*aw) - fmaxf(-0.5f*gw, -0.5f*aw);
                float ch = fminf(0.5f*gh, 0.5f*ah) - fmaxf(-0.5f*gh, -0.5f*ah);
                float ca = (cw <= 0.f || ch <= 0.f) ? 0.f : cw*ch;
                float iou = ca / (gw*gh + aw*ah - ca);
                if (iou > best) { best = iou; bn = a; }
            }
            int gi = (int)floorf(gx), gj = (int)floorf(gy);
            int cell = bn*HW + gj*NW + gi;
            int cc_i = (int)cc; if (cc_i < 0) cc_i = 0; if (cc_i > NC-1) cc_i = NC-1;
            sA[tid] = make_float4(gx - 0.5f*gw, gx + 0.5f*gw, gy - 0.5f*gh, gy + 0.5f*gh);
            sB[tid] = make_float2(gw*gh, __int_as_float(cell));
            sC[tid] = make_float4(gx - (float)gi, gy - (float)gj,
                                  logf(gw / c_AW[bn]), logf(gh / c_AH[bn]));
            sD[tid] = make_float2(sqrtf(2.f - w*h), __int_as_float(cc_i));
        } else {
            sA[tid] = make_float4(1e30f, -1e30f, 1e30f, -1e30f);  // overlap impossible
            sB[tid] = make_float2(0.f, __int_as_float(-1));       // cell never matches
            sC[tid] = make_float4(0.f, 0.f, 0.f, 0.f);
            sD[tid] = make_float2(0.f, __int_as_float(0));
        }
    }
    __syncthreads();

    // ---- per-cell prologue, 2 cells per thread ----
    int idx0 = blockIdx.x*CPB + tid;
    int idx1 = idx0 + BLK;
    bool v0 = idx0 < CELLS_PER_B;
    bool v1 = idx1 < CELLS_PER_B;

    float s0a=0.f, s1a=0.f, c2a=0.f, c3a=0.f, c4a=0.f;
    float px1a=1e30f, px2a=-1e30f, py1a=1e30f, py2a=-1e30f, paa=0.f;
    const float* o0 = out;
    if (v0) {
        int a  = idx0 / HW;
        int hw = idx0 - a*HW;
        int hh = hw / NW, ww = hw - hh*NW;
        o0 = out + (size_t)(b*255 + a*85)*HW + hw;
        float c0 = o0[0], c1 = o0[HW];
        c2a = o0[2*HW]; c3a = o0[3*HW]; c4a = o0[4*HW];
        s0a = __fdividef(1.f, 1.f + __expf(-c0));
        s1a = __fdividef(1.f, 1.f + __expf(-c1));
        int aq = (b*3 + a) >> 5;                       // faithful anchor-flatten quirk
        float pw = __expf(c2a)*c_AW[aq], ph = __expf(c3a)*c_AH[aq];
        float px = s0a + (float)ww, py = s1a + (float)hh;
        px1a = px - 0.5f*pw; px2a = px + 0.5f*pw;
        py1a = py - 0.5f*ph; py2a = py + 0.5f*ph;
        paa = pw*ph;
    }
    float s0b=0.f, s1b=0.f, c2b=0.f, c3b=0.f, c4b=0.f;
    float px1b=1e30f, px2b=-1e30f, py1b=1e30f, py2b=-1e30f, pab=0.f;
    const float* o1 = out;
    if (v1) {
        int a  = idx1 / HW;
        int hw = idx1 - a*HW;
        int hh = hw / NW, ww = hw - hh*NW;
        o1 = out + (size_t)(b*255 + a*85)*HW + hw;
        float c0 = o1[0], c1 = o1[HW];
        c2b = o1[2*HW]; c3b = o1[3*HW]; c4b = o1[4*HW];
        s0b = __fdividef(1.f, 1.f + __expf(-c0));
        s1b = __fdividef(1.f, 1.f + __expf(-c1));
        int aq = (b*3 + a) >> 5;
        float pw = __expf(c2b)*c_AW[aq], ph = __expf(c3b)*c_AH[aq];
        float px = s0b + (float)ww, py = s1b + (float)hh;
        px1b = px - 0.5f*pw; px2b = px + 0.5f*pw;
        py1b = py - 0.5f*ph; py2b = py + 0.5f*ph;
        pab = pw*ph;
    }
    int key0 = v0 ? idx0 : -2;    // sentinel cell is -1; -2 never matches
    int key1 = v1 ? idx1 : -2;

    // ---- hot loop: fixed 50 iterations, branch-free ----
    bool ign0 = false, ign1 = false;
    int  last0 = -1,  last1 = -1;
#pragma unroll 10
    for (int t2 = 0; t2 < MAXB; t2++) {
        float4 A = sA[t2];
        float2 B = sB[t2];
        int cellv = __float_as_int(B.y);
        // cell 0
        {
            float cw = fminf(px2a, A.y) - fmaxf(px1a, A.x);
            float ch = fminf(py2a, A.w) - fmaxf(py1a, A.z);
            bool hit = (cw > 0.f) && (ch > 0.f) && (3.f*(cw*ch) > paa + B.x);
            ign0 |= hit;
            if (cellv == key0) last0 = t2;
        }
        // cell 1
        {
            float cw = fminf(px2b, A.y) - fmaxf(px1b, A.x);
            float ch = fminf(py2b, A.w) - fmaxf(py1b, A.z);
            bool hit = (cw > 0.f) && (ch > 0.f) && (3.f*(cw*ch) > pab + B.x);
            ign1 |= hit;
            if (cellv == key1) last1 = t2;
        }
    }

    // ---- epilogue per cell ----
    float coordL = 0.f, confL = 0.f, clsL = 0.f;

    if (v0) {
        if (last0 >= 0) {
            confL += __logf(1.f + __expf(-c4a));                 // -log(conf)
            float4 tc = sC[last0]; float m = sD[last0].x;
            float d0 = s0a*m - tc.x*m, d1 = s1a*m - tc.y*m;
            float d2 = c2a*m - tc.z*m, d3 = c3a*m - tc.w*m;
            coordL += 0.5f*(d0*d0 + d1*d1 + d2*d2 + d3*d3);
            unsigned cb0=0u, cb1=0u, cb2=0u;
            for (int t2 = 0; t2 < MAXB; t2++) {
                if (__float_as_int(sB[t2].y) == idx0) {
                    int c = __float_as_int(sD[t2].y);
                    if (c < 32)      cb0 |= 1u << c;
                    else if (c < 64) cb1 |= 1u << (c - 32);
                    else             cb2 |= 1u << (c - 64);
                }
            }
#pragma unroll 4
            for (int c = 0; c < NC; c++) {
                float xv = o0[(5 + c)*HW];
                float sp = __logf(1.f + __expf(-xv));            // softplus(-xv)
                unsigned bit = ((c < 32) ? (cb0 >> c) : (c < 64) ? (cb1 >> (c-32)) : (cb2 >> (c-64))) & 1u;
                clsL += bit ? sp : (xv + sp);                    // -log(p) : -log(1-p)
            }
        } else if (!ign0) {
            confL += c4a + __logf(1.f + __expf(-c4a));           // -log(1-conf)
        }
    }
    if (v1) {
        if (last1 >= 0) {
            confL += __logf(1.f + __expf(-c4b));
            float4 tc = sC[last1]; float m = sD[last1].x;
            float d0 = s0b*m - tc.x*m, d1 = s1b*m - tc.y*m;
            float d2 = c2b*m - tc.z*m, d3 = c3b*m - tc.w*m;
            coordL += 0.5f*(d0*d0 + d1*d1 + d2*d2 + d3*d3);
            unsigned cb0=0u, cb1=0u, cb2=0u;
            for (int t2 = 0; t2 < MAXB; t2++) {
                if (__float_as_int(sB[t2].y) == idx1) {
                    int c = __float_as_int(sD[t2].y);
                    if (c < 32)      cb0 |= 1u << c;
                    else if (c < 64) cb1 |= 1u << (c - 32);
                    else             cb2 |= 1u << (c - 64);
                }
            }
#pragma unroll 4
            for (int c = 0; c < NC; c++) {
                float xv = o1[(5 + c)*HW];
                float sp = __logf(1.f + __expf(-xv));
                unsigned bit = ((c < 32) ? (cb0 >> c) : (c < 64) ? (cb1 >> (c-32)) : (cb2 >> (c-64))) & 1u;
                clsL += bit ? sp : (xv + sp);
            }
        } else if (!ign1) {
            confL += c4b + __logf(1.f + __expf(-c4b));
        }
    }

    // ---- block reduce 3 sums ----
    unsigned fm = 0xffffffffu;
#pragma unroll
    for (int off = 16; off; off >>= 1) {
        coordL += __shfl_down_sync(fm, coordL, off);
        confL  += __shfl_down_sync(fm, confL,  off);
        clsL   += __shfl_down_sync(fm, clsL,   off);
    }
    int lane = tid & 31, wrp = tid >> 5;
    if (lane == 0) { s_red[0][wrp] = coordL; s_red[1][wrp] = confL; s_red[2][wrp] = clsL; }
    __syncthreads();
    if (tid < 3) {
        float s = 0.f;
#pragma unroll
        for (int j = 0; j < BLK/32; j++) s += s_red[tid][j];
        g_partial[blockIdx.y*gridDim.x + blockIdx.x][tid] = s;
    }
}

// ---------------- deterministic final reduce ----------------
__global__ void __launch_bounds__(256) kC(float* __restrict__ dout) {
    __shared__ float s_red[3][8];
    float a0 = 0.f, a1 = 0.f, a2 = 0.f;
    for (int i = threadIdx.x; i < NPART; i += 256) {
        a0 += g_partial[i][0]; a1 += g_partial[i][1]; a2 += g_partial[i][2];
    }
    unsigned fm = 0xffffffffu;
#pragma unroll
    for (int off = 16; off; off >>= 1) {
        a0 += __shfl_down_sync(fm, a0, off);
        a1 += __shfl_down_sync(fm, a1, off);
        a2 += __shfl_down_sync(fm, a2, off);
    }
    int lane = threadIdx.x & 31, wrp = threadIdx.x >> 5;
    if (lane == 0) { s_red[0][wrp] = a0; s_red[1][wrp] = a1; s_red[2][wrp] = a2; }
    __syncthreads();
    if (threadIdx.x < 3) {
        float s = 0.f;
#pragma unroll
        for (int j = 0; j < 8; j++) s += s_red[threadIdx.x][j];
        dout[threadIdx.x] = s / (float)NB;
    }
}

extern "C" void kernel_launch(void* const* d_in, const int* in_sizes, int n_in,
                              void* d_out, int out_size) {
    const float* output = (const float*)d_in[0];
    const float* target = (const float*)d_in[1];
    if (n_in >= 2 && in_sizes[0] == NB*MAXB*5) {  // defensive: inputs swapped
        output = (const float*)d_in[1];
        target = (const float*)d_in[0];
    }
    dim3 g(GXB, NB);
    kB<<<g, BLK>>>(output, target);
    kC<<<1, 256>>>((float*)d_out);
}

// round 6
// speedup vs baseline: 1.9881x; 1.3895x over previous
#include <cuda_runtime.h>

#define NB 32
#define NA 3
#define NH 52
#define NW 52
#define NC 80
#define HW (NH*NW)                    // 2704
#define CELLS_PER_B (NA*HW)           // 8112
#define MAXB 50
#define BLK 256
#define NWARPS (BLK/32)
#define CPT 2
#define CPB (BLK*CPT)                 // 512
#define GXB ((CELLS_PER_B + CPB - 1)/CPB)  // 16
#define NPART (GXB*NB)                // 512
#define QMAX 64

__constant__ float c_AW[3] = {10.f/32.f, 16.f/32.f, 33.f/32.f};
__constant__ float c_AH[3] = {13.f/32.f, 30.f/32.f, 23.f/32.f};

__device__ float g_partial[NPART][3];
__device__ int   g_count = 0;

// ---------------- fully fused kernel ----------------
__global__ void __launch_bounds__(BLK) kF(const float* __restrict__ out,
                                          const float* __restrict__ target,
                                          float* __restrict__ dout) {
    __shared__ float4   sA[MAXB];   // {x1, x2, y1, y2} gt corners
    __shared__ float2   sB[MAXB];   // {garea, cell-as-int}
    __shared__ float4   sC[MAXB];   // {tx, ty, tw, th}
    __shared__ float2   sD[MAXB];   // {scale, cls-as-int}
    __shared__ unsigned s_bal[2];
    __shared__ float    s_red[3][NWARPS];
    __shared__ int      s_wcnt[NWARPS], s_wbase[NWARPS], s_qn;
    __shared__ int      s_qoff[QMAX];
    __shared__ unsigned s_qb0[QMAX], s_qb1[QMAX], s_qb2[QMAX];
    __shared__ int      s_islast;

    int b = blockIdx.y, tid = threadIdx.x;
    int lane = tid & 31, wid = tid >> 5;

    // ---- build gt table in shared (threads 0..49; ballot prefix over 2 warps) ----
    bool  ok = false;
    float cc = 0.f, x = 0.f, y = 0.f, w = 0.f, h = 0.f;
    if (tid < MAXB) {
        const float* tp = target + b*MAXB*5 + tid*5;
        cc = tp[0]; x = tp[1]; y = tp[2]; w = tp[3]; h = tp[4];
        ok = (x != 0.f);
    }
    if (tid < 64) {
        unsigned bal = __ballot_sync(0xffffffffu, ok);
        if (lane == 0) s_bal[wid] = bal;
    }
    __syncthreads();
    if (tid < MAXB) {
        bool valid;
        if (tid < 32) {
            unsigned low = (tid == 31) ? 0xffffffffu : ((1u << (tid + 1)) - 1u);
            valid = ((s_bal[0] & low) == low);
        } else {
            unsigned low = (1u << (tid - 31)) - 1u;
            valid = (s_bal[0] == 0xffffffffu) && ((s_bal[1] & low) == low);
        }
        if (valid) {
            float gx = x*(float)NW, gy = y*(float)NH;
            float gw = w*(float)NW, gh = h*(float)NH;
            int bn = 0; float best = -1e30f;
#pragma unroll
            for (int a = 0; a < 3; a++) {
                float aw = c_AW[a], ah = c_AH[a];
                float cw = fminf(0.5f*gw, 0.5f*aw) - fmaxf(-0.5f*gw, -0.5f*aw);
                float ch = fminf(0.5f*gh, 0.5f*ah) - fmaxf(-0.5f*gh, -0.5f*ah);
                float ca = (cw <= 0.f || ch <= 0.f) ? 0.f : cw*ch;
                float iou = ca / (gw*gh + aw*ah - ca);
                if (iou > best) { best = iou; bn = a; }
            }
            int gi = (int)floorf(gx), gj = (int)floorf(gy);
            int cell = bn*HW + gj*NW + gi;
            int cc_i = (int)cc; if (cc_i < 0) cc_i = 0; if (cc_i > NC-1) cc_i = NC-1;
            sA[tid] = make_float4(gx - 0.5f*gw, gx + 0.5f*gw, gy - 0.5f*gh, gy + 0.5f*gh);
            sB[tid] = make_float2(gw*gh, __int_as_float(cell));
            sC[tid] = make_float4(gx - (float)gi, gy - (float)gj,
                                  logf(gw / c_AW[bn]), logf(gh / c_AH[bn]));
            sD[tid] = make_float2(sqrtf(2.f - w*h), __int_as_float(cc_i));
        } else {
            sA[tid] = make_float4(1e30f, -1e30f, 1e30f, -1e30f);
            sB[tid] = make_float2(0.f, __int_as_float(-1));
            sC[tid] = make_float4(0.f, 0.f, 0.f, 0.f);
            sD[tid] = make_float2(0.f, __int_as_float(0));
        }
    }
    __syncthreads();

    // ---- per-cell prologue, 2 cells per thread ----
    int idx0 = blockIdx.x*CPB + tid;
    int idx1 = idx0 + BLK;
    bool v0 = idx0 < CELLS_PER_B;
    bool v1 = idx1 < CELLS_PER_B;

    float s0a=0.f, s1a=0.f, c2a=0.f, c3a=0.f, c4a=0.f;
    float px1a=1e30f, px2a=-1e30f, py1a=1e30f, py2a=-1e30f, paa=0.f;
    int off0 = 0;
    if (v0) {
        int a  = idx0 / HW;
        int hw = idx0 - a*HW;
        int hh = hw / NW, ww = hw - hh*NW;
        off0 = (b*255 + a*85)*HW + hw;
        const float* o0 = out + off0;
        float c0 = o0[0], c1 = o0[HW];
        c2a = o0[2*HW]; c3a = o0[3*HW]; c4a = o0[4*HW];
        s0a = __fdividef(1.f, 1.f + __expf(-c0));
        s1a = __fdividef(1.f, 1.f + __expf(-c1));
        int aq = (b*3 + a) >> 5;                       // faithful anchor-flatten quirk
        float pw = __expf(c2a)*c_AW[aq], ph = __expf(c3a)*c_AH[aq];
        float px = s0a + (float)ww, py = s1a + (float)hh;
        px1a = px - 0.5f*pw; px2a = px + 0.5f*pw;
        py1a = py - 0.5f*ph; py2a = py + 0.5f*ph;
        paa = pw*ph;
    }
    float s0b=0.f, s1b=0.f, c2b=0.f, c3b=0.f, c4b=0.f;
    float px1b=1e30f, px2b=-1e30f, py1b=1e30f, py2b=-1e30f, pab=0.f;
    int off1 = 0;
    if (v1) {
        int a  = idx1 / HW;
        int hw = idx1 - a*HW;
        int hh = hw / NW, ww = hw - hh*NW;
        off1 = (b*255 + a*85)*HW + hw;
        const float* o1 = out + off1;
        float c0 = o1[0], c1 = o1[HW];
        c2b = o1[2*HW]; c3b = o1[3*HW]; c4b = o1[4*HW];
        s0b = __fdividef(1.f, 1.f + __expf(-c0));
        s1b = __fdividef(1.f, 1.f + __expf(-c1));
        int aq = (b*3 + a) >> 5;
        float pw = __expf(c2b)*c_AW[aq], ph = __expf(c3b)*c_AH[aq];
        float px = s0b + (float)ww, py = s1b + (float)hh;
        px1b = px - 0.5f*pw; px2b = px + 0.5f*pw;
        py1b = py - 0.5f*ph; py2b = py + 0.5f*ph;
        pab = pw*ph;
    }
    int key0 = v0 ? idx0 : -2;
    int key1 = v1 ? idx1 : -2;

    // ---- hot loop: fixed 50 iterations, branch-free ----
    bool ign0 = false, ign1 = false;
    int  last0 = -1,  last1 = -1;
#pragma unroll 10
    for (int t2 = 0; t2 < MAXB; t2++) {
        float4 A = sA[t2];
        float2 B = sB[t2];
        int cellv = __float_as_int(B.y);
        {
            float cw = fminf(px2a, A.y) - fmaxf(px1a, A.x);
            float ch = fminf(py2a, A.w) - fmaxf(py1a, A.z);
            ign0 |= (cw > 0.f) && (ch > 0.f) && (3.f*(cw*ch) > paa + B.x);
            if (cellv == key0) last0 = t2;
        }
        {
            float cw = fminf(px2b, A.y) - fmaxf(px1b, A.x);
            float ch = fminf(py2b, A.w) - fmaxf(py1b, A.z);
            ign1 |= (cw > 0.f) && (ch > 0.f) && (3.f*(cw*ch) > pab + B.x);
            if (cellv == key1) last1 = t2;
        }
    }

    // ---- deterministic compaction of object cells into shared queue ----
    unsigned m0 = __ballot_sync(0xffffffffu, last0 >= 0);
    unsigned m1 = __ballot_sync(0xffffffffu, last1 >= 0);
    if (lane == 0) s_wcnt[wid] = __popc(m0) + __popc(m1);
    __syncthreads();
    if (tid == 0) {
        int acc = 0;
#pragma unroll
        for (int j = 0; j < NWARPS; j++) { s_wbase[j] = acc; acc += s_wcnt[j]; }
        s_qn = acc;
    }
    __syncthreads();

    float coordL = 0.f, confL = 0.f, clsL = 0.f;
    unsigned ltm = (1u << lane) - 1u;

    if (last0 >= 0) {
        confL += __logf(1.f + __expf(-c4a));                 // -log(conf)
        float4 tc = sC[last0]; float m = sD[last0].x;
        float d0 = s0a*m - tc.x*m, d1 = s1a*m - tc.y*m;
        float d2 = c2a*m - tc.z*m, d3 = c3a*m - tc.w*m;
        coordL += 0.5f*(d0*d0 + d1*d1 + d2*d2 + d3*d3);
        unsigned cb0=0u, cb1=0u, cb2=0u;
        for (int t2 = 0; t2 < MAXB; t2++) {
            if (__float_as_int(sB[t2].y) == idx0) {
                int c = __float_as_int(sD[t2].y);
                if (c < 32)      cb0 |= 1u << c;
                else if (c < 64) cb1 |= 1u << (c - 32);
                else             cb2 |= 1u << (c - 64);
            }
        }
        int q = s_wbase[wid] + __popc(m0 & ltm);
        s_qoff[q] = off0; s_qb0[q] = cb0; s_qb1[q] = cb1; s_qb2[q] = cb2;
    } else if (v0 && !ign0) {
        confL += c4a + __logf(1.f + __expf(-c4a));           // -log(1-conf)
    }
    if (last1 >= 0) {
        confL += __logf(1.f + __expf(-c4b));
        float4 tc = sC[last1]; float m = sD[last1].x;
        float d0 = s0b*m - tc.x*m, d1 = s1b*m - tc.y*m;
        float d2 = c2b*m - tc.z*m, d3 = c3b*m - tc.w*m;
        coordL += 0.5f*(d0*d0 + d1*d1 + d2*d2 + d3*d3);
        unsigned cb0=0u, cb1=0u, cb2=0u;
        for (int t2 = 0; t2 < MAXB; t2++) {
            if (__float_as_int(sB[t2].y) == idx1) {
                int c = __float_as_int(sD[t2].y);
                if (c < 32)      cb0 |= 1u << c;
                else if (c < 64) cb1 |= 1u << (c - 32);
                else             cb2 |= 1u << (c - 64);
            }
        }
        int q = s_wbase[wid] + __popc(m0) + __popc(m1 & ltm);
        s_qoff[q] = off1; s_qb0[q] = cb0; s_qb1[q] = cb1; s_qb2[q] = cb2;
    } else if (v1 && !ign1) {
        confL += c4b + __logf(1.f + __expf(-c4b));
    }
    __syncthreads();

    // ---- warp-cooperative class loss: 80 classes split over 32 lanes ----
    int qn = s_qn;
    for (int e = wid; e < qn; e += NWARPS) {
        int base = s_qoff[e] + 5*HW;
        unsigned cb0 = s_qb0[e], cb1 = s_qb1[e], cb2 = s_qb2[e];
        int c0i = lane, c1i = lane + 32, c2i = lane + 64;
        float xv0 = out[base + c0i*HW];
        float xv1 = out[base + c1i*HW];
        float xv2 = (c2i < NC) ? out[base + c2i*HW] : 0.f;
        float sp0 = __logf(1.f + __expf(-xv0));
        float sp1 = __logf(1.f + __expf(-xv1));
        float sp2 = __logf(1.f + __expf(-xv2));
        unsigned b0 = (cb0 >> c0i) & 1u;
        unsigned b1 = (cb1 >> (c1i - 32)) & 1u;
        unsigned b2 = (c2i < NC) ? ((cb2 >> (c2i - 64)) & 1u) : 1u;
        clsL += b0 ? sp0 : (xv0 + sp0);
        clsL += b1 ? sp1 : (xv1 + sp1);
        clsL += (c2i < NC) ? (b2 ? sp2 : (xv2 + sp2)) : 0.f;
    }

    // ---- block reduce 3 sums ----
    unsigned fm = 0xffffffffu;
#pragma unroll
    for (int off = 16; off; off >>= 1) {
        coordL += __shfl_down_sync(fm, coordL, off);
        confL  += __shfl_down_sync(fm, confL,  off);
        clsL   += __shfl_down_sync(fm, clsL,   off);
    }
    if (lane == 0) { s_red[0][wid] = coordL; s_red[1][wid] = confL; s_red[2][wid] = clsL; }
    __syncthreads();
    if (tid < 3) {
        float s = 0.f;
#pragma unroll
        for (int j = 0; j < NWARPS; j++) s += s_red[tid][j];
        g_partial[blockIdx.y*gridDim.x + blockIdx.x][tid] = s;
    }
    __threadfence();
    if (tid == 0) {
        int t = atomicAdd(&g_count, 1);
        s_islast = (t == NPART - 1) ? 1 : 0;
    }
    __syncthreads();

    // ---- last block: deterministic final reduce ----
    if (s_islast) {
        volatile float* gp = &g_partial[0][0];
        float a0 = 0.f, a1 = 0.f, a2 = 0.f;
        for (int i = tid; i < NPART; i += BLK) {
            a0 += gp[i*3 + 0]; a1 += gp[i*3 + 1]; a2 += gp[i*3 + 2];
        }
#pragma unroll
        for (int off = 16; off; off >>= 1) {
            a0 += __shfl_down_sync(fm, a0, off);
            a1 += __shfl_down_sync(fm, a1, off);
            a2 += __shfl_down_sync(fm, a2, off);
        }
        __shared__ float s_fin[3][NWARPS];
        if (lane == 0) { s_fin[0][wid] = a0; s_fin[1][wid] = a1; s_fin[2][wid] = a2; }
        __syncthreads();
        if (tid < 3) {
            float s = 0.f;
#pragma unroll
            for (int j = 0; j < NWARPS; j++) s += s_fin[tid][j];
            dout[tid] = s / (float)NB;
        }
        if (tid == 0) g_count = 0;     // reset for next graph replay
    }
}

extern "C" void kernel_launch(void* const* d_in, const int* in_sizes, int n_in,
                              void* d_out, int out_size) {
    const float* output = (const float*)d_in[0];
    const float* target = (const float*)d_in[1];
    if (n_in >= 2 && in_sizes[0] == NB*MAXB*5) {  // defensive: inputs swapped
        output = (const float*)d_in[1];
        target = (const float*)d_in[0];
    }
    dim3 g(GXB, NB);
    kF<<<g, BLK>>>(output, target, (float*)d_out);
}

// round 8
// speedup vs baseline: 2.3503x; 1.1822x over previous
#include <cuda_runtime.h>

#define NB 32
#define NA 3
#define NH 52
#define NW 52
#define NC 80
#define HW (NH*NW)                    // 2704
#define CELLS_PER_B (NA*HW)           // 8112
#define MAXB 50
#define BLK 256
#define NWARPS (BLK/32)
#define CPT 2
#define CPB (BLK*CPT)                 // 512
#define GXB ((CELLS_PER_B + CPB - 1)/CPB)  // 16
#define NPART (GXB*NB)                // 512
#define QMAX 64

__constant__ float c_AW[3] = {10.f/32.f, 16.f/32.f, 33.f/32.f};
__constant__ float c_AH[3] = {13.f/32.f, 30.f/32.f, 23.f/32.f};

__device__ float g_partial[NPART][3];
__device__ int   g_count = 0;

// FMA-pipe exp: magic-number round-to-nearest + deg-6 Taylor for 2^f, exponent splice.
// |rel err| ~2e-7 for |x| <= ~50. No MUFU.
__device__ __forceinline__ float pexp(float x) {
    float y = x * 1.4426950408889634f;
    y = fminf(fmaxf(y, -80.f), 80.f);
    float fm = y + 12582912.f;                    // 1.5*2^23
    int   i  = __float_as_int(fm) - 0x4B400000;   // round(y) as int
    float r  = fm - 12582912.f;
    float f  = y - r;                             // f in [-0.5, 0.5]
    float p  =          1.54035304e-4f;
    p = p*f + 1.33335581e-3f;
    p = p*f + 9.61812911e-3f;
    p = p*f + 5.55041087e-2f;
    p = p*f + 2.40226507e-1f;
    p = p*f + 6.93147182e-1f;
    p = p*f + 1.f;                                // 2^f
    return __int_as_float(__float_as_int(p) + (i << 23));
}

// ---------------- fully fused kernel ----------------
__global__ void __launch_bounds__(BLK) kF(const float* __restrict__ out,
                                          const float* __restrict__ target,
                                          float* __restrict__ dout) {
    __shared__ float4   sH[MAXB];     // {3*x1, 3*x2, y1, y2} gt corners (x pre-scaled by 3)
    __shared__ float    sNga[MAXB];   // -garea
    __shared__ float4   sC[MAXB];     // {tx, ty, tw, th}
    __shared__ float2   sD[MAXB];     // {scale, cls-as-int}
    __shared__ int      sCell[MAXB];  // target cell (-1 invalid)
    __shared__ int      s_last[CPB];  // last gt slot targeting each local cell
    __shared__ unsigned s_bal[2];
    __shared__ float    s_red[3][NWARPS];
    __shared__ int      s_wcnt[NWARPS], s_wbase[NWARPS], s_qn;
    __shared__ int      s_qoff[QMAX];
    __shared__ unsigned s_qb0[QMAX], s_qb1[QMAX], s_qb2[QMAX];
    __shared__ int      s_islast;

    int b = blockIdx.y, tid = threadIdx.x;
    int lane = tid & 31, wid = tid >> 5;
    int base = blockIdx.x*CPB;

    // ---- phase 1: read targets, ballot validity, init s_last ----
    bool  ok = false;
    float cc = 0.f, x = 0.f, y = 0.f, w = 0.f, h = 0.f;
    if (tid < MAXB) {
        const float* tp = target + b*MAXB*5 + tid*5;
        cc = tp[0]; x = tp[1]; y = tp[2]; w = tp[3]; h = tp[4];
        ok = (x != 0.f);
    }
    if (tid < 64) {
        unsigned bal = __ballot_sync(0xffffffffu, ok);
        if (lane == 0) s_bal[wid] = bal;
    }
    s_last[tid] = -1;
    s_last[tid + BLK] = -1;
    __syncthreads();

    // ---- phase 2: build gt table + scatter cell ownership ----
    if (tid < MAXB) {
        bool valid;
        if (tid < 32) {
            unsigned low = (tid == 31) ? 0xffffffffu : ((1u << (tid + 1)) - 1u);
            valid = ((s_bal[0] & low) == low);
        } else {
            unsigned low = (1u << (tid - 31)) - 1u;
            valid = (s_bal[0] == 0xffffffffu) && ((s_bal[1] & low) == low);
        }
        if (valid) {
            float gx = x*(float)NW, gy = y*(float)NH;
            float gw = w*(float)NW, gh = h*(float)NH;
            int bn = 0; float best = -1e30f;
#pragma unroll
            for (int a = 0; a < 3; a++) {
                float aw = c_AW[a], ah = c_AH[a];
                float cw = fminf(0.5f*gw, 0.5f*aw) - fmaxf(-0.5f*gw, -0.5f*aw);
                float ch = fminf(0.5f*gh, 0.5f*ah) - fmaxf(-0.5f*gh, -0.5f*ah);
                float ca = (cw <= 0.f || ch <= 0.f) ? 0.f : cw*ch;
                float iou = ca / (gw*gh + aw*ah - ca);
                if (iou > best) { best = iou; bn = a; }
            }
            int gi = (int)floorf(gx), gj = (int)floorf(gy);
            int cell = bn*HW + gj*NW + gi;
            int cc_i = (int)cc; if (cc_i < 0) cc_i = 0; if (cc_i > NC-1) cc_i = NC-1;
            sH[tid]   = make_float4(3.f*(gx - 0.5f*gw), 3.f*(gx + 0.5f*gw),
                                    gy - 0.5f*gh, gy + 0.5f*gh);
            sNga[tid] = -(gw*gh);
            sC[tid]   = make_float4(gx - (float)gi, gy - (float)gj,
                                    logf(gw / c_AW[bn]), logf(gh / c_AH[bn]));
            sD[tid]   = make_float2(sqrtf(2.f - w*h), __int_as_float(cc_i));
            sCell[tid] = cell;
            int c = cell - base;
            if (c >= 0 && c < CPB) atomicMax(&s_last[c], tid);
        } else {
            sH[tid]   = make_float4(1e38f, -1e38f, 1e38f, -1e38f);
            sNga[tid] = -1e30f;
            sC[tid]   = make_float4(0.f, 0.f, 0.f, 0.f);
            sD[tid]   = make_float2(0.f, __int_as_float(0));
            sCell[tid] = -1;
        }
    }
    __syncthreads();

    // ---- per-cell prologue, 2 cells per thread (FMA-pipe exp, 1 RCP/cell) ----
    int idx0 = base + tid;
    int idx1 = idx0 + BLK;
    bool v0 = idx0 < CELLS_PER_B;
    bool v1 = idx1 < CELLS_PER_B;

    float s0a=0.f, s1a=0.f, c2a=0.f, c3a=0.f, c4a=0.f, paa=0.f;
    float px1a=1e38f, px2a=-1e38f, py1a=1e38f, py2a=-1e38f;
    int off0 = 0;
    if (v0) {
        int a  = idx0 / HW;
        int hw = idx0 - a*HW;
        int hh = hw / NW, ww = hw - hh*NW;
        off0 = (b*255 + a*85)*HW + hw;
        const float* o0 = out + off0;
        float c0 = o0[0], c1 = o0[HW];
        c2a = o0[2*HW]; c3a = o0[3*HW]; c4a = o0[4*HW];
        float u0 = pexp(-c0), u1 = pexp(-c1);
        float d0 = 1.f + u0, d1 = 1.f + u1;
        float rr = __fdividef(1.f, d0*d1);          // single MUFU.RCP
        s0a = d1*rr; s1a = d0*rr;
        int aq = (b*3 + a) >> 5;                    // faithful anchor-flatten quirk
        float pw = pexp(c2a)*c_AW[aq], ph = pexp(c3a)*c_AH[aq];
        float px = s0a + (float)ww, py = s1a + (float)hh;
        px1a = 3.f*(px - 0.5f*pw); px2a = 3.f*(px + 0.5f*pw);
        py1a = py - 0.5f*ph;       py2a = py + 0.5f*ph;
        paa = pw*ph;
    }
    float s0b=0.f, s1b=0.f, c2b=0.f, c3b=0.f, c4b=0.f, pab=0.f;
    float px1b=1e38f, px2b=-1e38f, py1b=1e38f, py2b=-1e38f;
    int off1 = 0;
    if (v1) {
        int a  = idx1 / HW;
        int hw = idx1 - a*HW;
        int hh = hw / NW, ww = hw - hh*NW;
        off1 = (b*255 + a*85)*HW + hw;
        const float* o1 = out + off1;
        float c0 = o1[0], c1 = o1[HW];
        c2b = o1[2*HW]; c3b = o1[3*HW]; c4b = o1[4*HW];
        float u0 = pexp(-c0), u1 = pexp(-c1);
        float d0 = 1.f + u0, d1 = 1.f + u1;
        float rr = __fdividef(1.f, d0*d1);
        s0b = d1*rr; s1b = d0*rr;
        int aq = (b*3 + a) >> 5;
        float pw = pexp(c2b)*c_AW[aq], ph = pexp(c3b)*c_AH[aq];
        float px = s0b + (float)ww, py = s1b + (float)hh;
        px1b = 3.f*(px - 0.5f*pw); px2b = 3.f*(px + 0.5f*pw);
        py1b = py - 0.5f*ph;       py2b = py + 0.5f*ph;
        pab = pw*ph;
    }

    // ---- hot loop: fixed 50 iterations, 10 FP ops per cell per gt ----
    float dmax0 = -1e30f, dmax1 = -1e30f;
#pragma unroll 10
    for (int t2 = 0; t2 < MAXB; t2++) {
        float4 A  = sH[t2];
        float nga = sNga[t2];
        {
            float cw = fmaxf(fminf(px2a, A.y) - fmaxf(px1a, A.x), 0.f);
            float ch = fmaxf(fminf(py2a, A.w) - fmaxf(py1a, A.z), 0.f);
            dmax0 = fmaxf(dmax0, fmaf(cw, ch, nga));   // 3*ca - ga  (x pre-scaled by 3)
        }
        {
            float cw = fmaxf(fminf(px2b, A.y) - fmaxf(px1b, A.x), 0.f);
            float ch = fmaxf(fminf(py2b, A.w) - fmaxf(py1b, A.z), 0.f);
            dmax1 = fmaxf(dmax1, fmaf(cw, ch, nga));
        }
    }
    bool ign0 = dmax0 > paa;       // 3*ca > pa + ga  <=>  iou > 0.5
    bool ign1 = dmax1 > pab;
    int last0 = s_last[tid];
    int last1 = s_last[tid + BLK];

    // ---- deterministic compaction of object cells into shared queue ----
    unsigned m0 = __ballot_sync(0xffffffffu, last0 >= 0);
    unsigned m1 = __ballot_sync(0xffffffffu, last1 >= 0);
    if (lane == 0) s_wcnt[wid] = __popc(m0) + __popc(m1);
    __syncthreads();
    if (tid == 0) {
        int acc = 0;
#pragma unroll
        for (int j = 0; j < NWARPS; j++) { s_wbase[j] = acc; acc += s_wcnt[j]; }
        s_qn = acc;
    }
    __syncthreads();

    float coordL = 0.f, confL = 0.f, clsL = 0.f;
    unsigned ltm = (1u << lane) - 1u;

    // conf loss: merged-log form.  obj: log(1+e^-c4);  back: c4 + log(1+e^-c4);  ign: 0
    {
        bool inc0 = v0 && (last0 >= 0 || !ign0);
        bool inc1 = v1 && (last1 >= 0 || !ign1);
        float t0 = inc0 ? (1.f + pexp(-c4a)) : 1.f;
        float t1 = inc1 ? (1.f + pexp(-c4b)) : 1.f;
        if (inc0 && last0 < 0) confL += c4a;
        if (inc1 && last1 < 0) confL += c4b;
        confL += __logf(t0 * t1);                   // one MUFU.LG2 per thread
    }

    if (last0 >= 0) {
        float4 tc = sC[last0]; float m = sD[last0].x;
        float d0 = s0a*m - tc.x*m, d1 = s1a*m - tc.y*m;
        float d2 = c2a*m - tc.z*m, d3 = c3a*m - tc.w*m;
        coordL += 0.5f*(d0*d0 + d1*d1 + d2*d2 + d3*d3);
        unsigned cb0=0u, cb1=0u, cb2=0u;
        for (int t2 = 0; t2 < MAXB; t2++) {
            if (sCell[t2] == idx0) {
                int c = __float_as_int(sD[t2].y);
                if (c < 32)      cb0 |= 1u << c;
                else if (c < 64) cb1 |= 1u << (c - 32);
                else             cb2 |= 1u << (c - 64);
            }
        }
        int q = s_wbase[wid] + __popc(m0 & ltm);
        s_qoff[q] = off0; s_qb0[q] = cb0; s_qb1[q] = cb1; s_qb2[q] = cb2;
    }
    if (last1 >= 0) {
        float4 tc = sC[last1]; float m = sD[last1].x;
        float d0 = s0b*m - tc.x*m, d1 = s1b*m - tc.y*m;
        float d2 = c2b*m - tc.z*m, d3 = c3b*m - tc.w*m;
        coordL += 0.5f*(d0*d0 + d1*d1 + d2*d2 + d3*d3);
        unsigned cb0=0u, cb1=0u, cb2=0u;
        for (int t2 = 0; t2 < MAXB; t2++) {
            if (sCell[t2] == idx1) {
                int c = __float_as_int(sD[t2].y);
                if (c < 32)      cb0 |= 1u << c;
                else if (c < 64) cb1 |= 1u << (c - 32);
                else             cb2 |= 1u << (c - 64);
            }
        }
        int q = s_wbase[wid] + __popc(m0) + __popc(m1 & ltm);
        s_qoff[q] = off1; s_qb0[q] = cb0; s_qb1[q] = cb1; s_qb2[q] = cb2;
    }
    __syncthreads();

    // ---- warp-cooperative class loss: 80 classes over 32 lanes, merged log ----
    int qn = s_qn;
    for (int e = wid; e < qn; e += NWARPS) {
        int basec = s_qoff[e] + 5*HW;
        unsigned cb0 = s_qb0[e], cb1 = s_qb1[e], cb2 = s_qb2[e];
        int c0i = lane, c1i = lane + 32, c2i = lane + 64;
        bool has2 = (c2i < NC);
        float xv0 = out[basec + c0i*HW];
        float xv1 = out[basec + c1i*HW];
        float xv2 = has2 ? out[basec + c2i*HW] : 0.f;
        float t0 = 1.f + pexp(-xv0);
        float t1 = 1.f + pexp(-xv1);
        float t2 = has2 ? (1.f + pexp(-xv2)) : 1.f;
        clsL += __logf(t0 * t1 * t2);               // merged: one LG2 per 3 classes
        if (!((cb0 >> c0i) & 1u)) clsL += xv0;
        if (!((cb1 >> (c1i - 32)) & 1u)) clsL += xv1;
        if (has2 && !((cb2 >> (c2i - 64)) & 1u)) clsL += xv2;
    }

    // ---- block reduce 3 sums ----
    unsigned fm = 0xffffffffu;
#pragma unroll
    for (int off = 16; off; off >>= 1) {
        coordL += __shfl_down_sync(fm, coordL, off);
        confL  += __shfl_down_sync(fm, confL,  off);
        clsL   += __shfl_down_sync(fm, clsL,   off);
    }
    if (lane == 0) { s_red[0][wid] = coordL; s_red[1][wid] = confL; s_red[2][wid] = clsL; }
    __syncthreads();
    if (tid < 3) {
        float s = 0.f;
#pragma unroll
        for (int j = 0; j < NWARPS; j++) s += s_red[tid][j];
        g_partial[blockIdx.y*gridDim.x + blockIdx.x][tid] = s;
    }
    __threadfence();
    if (tid == 0) {
        int t = atomicAdd(&g_count, 1);
        s_islast = (t == NPART - 1) ? 1 : 0;
    }
    __syncthreads();

    // ---- last block: deterministic final reduce ----
    if (s_islast) {
        volatile float* gp = &g_partial[0][0];
        float a0 = 0.f, a1 = 0.f, a2 = 0.f;
        for (int i = tid; i < NPART; i += BLK) {
            a0 += gp[i*3 + 0]; a1 += gp[i*3 + 1]; a2 += gp[i*3 + 2];
        }
#pragma unroll
        for (int off = 16; off; off >>= 1) {
            a0 += __shfl_down_sync(fm, a0, off);
            a1 += __shfl_down_sync(fm, a1, off);
            a2 += __shfl_down_sync(fm, a2, off);
        }
        __shared__ float s_fin[3][NWARPS];
        if (lane == 0) { s_fin[0][wid] = a0; s_fin[1][wid] = a1; s_fin[2][wid] = a2; }
        __syncthreads();
        if (tid < 3) {
            float s = 0.f;
#pragma unroll
            for (int j = 0; j < NWARPS; j++) s += s_fin[tid][j];
            dout[tid] = s / (float)NB;
        }
        if (tid == 0) g_count = 0;     // reset for next graph replay
    }
}

extern "C" void kernel_launch(void* const* d_in, const int* in_sizes, int n_in,
                              void* d_out, int out_size) {
    const float* output = (const float*)d_in[0];
    const float* target = (const float*)d_in[1];
    if (n_in >= 2 && in_sizes[0] == NB*MAXB*5) {  // defensive: inputs swapped
        output = (const float*)d_in[1];
        target = (const float*)d_in[0];
    }
    dim3 g(GXB, NB);
    kF<<<g, BLK>>>(output, target, (float*)d_out);
}

// round 9
// speedup vs baseline: 2.4725x; 1.0520x over previous
#include <cuda_runtime.h>

#define NB 32
#define NA 3
#define NH 52
#define NW 52
#define NC 80
#define HW (NH*NW)                    // 2704
#define CELLS_PER_B (NA*HW)           // 8112
#define MAXB 50
#define GTPAD 52                      // padded gt slots (13 groups of 4)
#define BLK 256
#define NWARPS (BLK/32)
#define CPT 2
#define CPB (BLK*CPT)                 // 512
#define GXB ((CELLS_PER_B + CPB - 1)/CPB)  // 16
#define NPART (GXB*NB)                // 512
#define QMAX 64

__constant__ float c_AW[3] = {10.f/32.f, 16.f/32.f, 33.f/32.f};
__constant__ float c_AH[3] = {13.f/32.f, 30.f/32.f, 23.f/32.f};

__device__ float g_partial[NPART][3];
__device__ int   g_count = 0;

// FMA-pipe exp: magic-number round-to-nearest + deg-6 Taylor for 2^f, exponent splice.
__device__ __forceinline__ float pexp(float x) {
    float y = x * 1.4426950408889634f;
    y = fminf(fmaxf(y, -80.f), 80.f);
    float fm = y + 12582912.f;                    // 1.5*2^23
    int   i  = __float_as_int(fm) - 0x4B400000;
    float r  = fm - 12582912.f;
    float f  = y - r;                             // f in [-0.5, 0.5]
    float p  =          1.54035304e-4f;
    p = p*f + 1.33335581e-3f;
    p = p*f + 9.61812911e-3f;
    p = p*f + 5.55041087e-2f;
    p = p*f + 2.40226507e-1f;
    p = p*f + 6.93147182e-1f;
    p = p*f + 1.f;                                // 2^f
    return __int_as_float(__float_as_int(p) + (i << 23));
}

// ---------------- fully fused kernel ----------------
__global__ void __launch_bounds__(BLK) kF(const float* __restrict__ out,
                                          const float* __restrict__ target,
                                          float* __restrict__ dout) {
    __shared__ float4   sH[GTPAD];    // {3*x1, 3*x2, y1, y2} (x pre-scaled by 3)
    __shared__ float4   sNga4[GTPAD/4];  // -garea packed 4/gt-group
    __shared__ float4   sC[MAXB];     // {tx, ty, tw, th}
    __shared__ float2   sD[MAXB];     // {scale, cls-as-int}
    __shared__ int      sCell[MAXB];  // target cell (-1 invalid)
    __shared__ int      s_last[CPB];  // last gt slot targeting each local cell
    __shared__ unsigned s_bal[2];
    __shared__ float    s_red[3][NWARPS];
    __shared__ int      s_wcnt[NWARPS], s_wbase[NWARPS], s_qn;
    __shared__ int      s_qoff[QMAX];
    __shared__ unsigned s_qb0[QMAX], s_qb1[QMAX], s_qb2[QMAX];
    __shared__ int      s_islast;

    int b = blockIdx.y, tid = threadIdx.x;
    int lane = tid & 31, wid = tid >> 5;
    int base = blockIdx.x*CPB;

    // ---- PREFETCH: issue all 10 channel loads before any shared-memory phase ----
    int idx0 = base + tid;
    int idx1 = idx0 + BLK;
    bool v0 = idx0 < CELLS_PER_B;
    bool v1 = idx1 < CELLS_PER_B;
    int i0 = v0 ? idx0 : 0;
    int i1 = v1 ? idx1 : 0;
    int a0 = i0 / HW, hw0 = i0 - a0*HW;
    int a1 = i1 / HW, hw1 = i1 - a1*HW;
    int off0 = (b*255 + a0*85)*HW + hw0;
    int off1 = (b*255 + a1*85)*HW + hw1;
    const float* o0 = out + off0;
    const float* o1 = out + off1;
    float L00 = __ldg(o0 + 0*HW), L01 = __ldg(o0 + 1*HW), L02 = __ldg(o0 + 2*HW),
          L03 = __ldg(o0 + 3*HW), L04 = __ldg(o0 + 4*HW);
    float L10 = __ldg(o1 + 0*HW), L11 = __ldg(o1 + 1*HW), L12 = __ldg(o1 + 2*HW),
          L13 = __ldg(o1 + 3*HW), L14 = __ldg(o1 + 4*HW);

    // ---- phase 1: read targets, ballot validity, init s_last ----
    bool  ok = false;
    float cc = 0.f, x = 0.f, y = 0.f, w = 0.f, h = 0.f;
    if (tid < MAXB) {
        const float* tp = target + b*MAXB*5 + tid*5;
        cc = tp[0]; x = tp[1]; y = tp[2]; w = tp[3]; h = tp[4];
        ok = (x != 0.f);
    }
    if (tid < 64) {
        unsigned bal = __ballot_sync(0xffffffffu, ok);
        if (lane == 0) s_bal[wid] = bal;
    }
    s_last[tid] = -1;
    s_last[tid + BLK] = -1;
    __syncthreads();

    // ---- phase 2: build gt table + scatter cell ownership ----
    if (tid < GTPAD) {
        bool valid = false;
        if (tid < MAXB) {
            if (tid < 32) {
                unsigned low = (tid == 31) ? 0xffffffffu : ((1u << (tid + 1)) - 1u);
                valid = ((s_bal[0] & low) == low);
            } else {
                unsigned low = (1u << (tid - 31)) - 1u;
                valid = (s_bal[0] == 0xffffffffu) && ((s_bal[1] & low) == low);
            }
        }
        if (valid) {
            float gx = x*(float)NW, gy = y*(float)NH;
            float gw = w*(float)NW, gh = h*(float)NH;
            int bn = 0; float best = -1e30f;
#pragma unroll
            for (int a = 0; a < 3; a++) {
                float aw = c_AW[a], ah = c_AH[a];
                float cw = fminf(0.5f*gw, 0.5f*aw) - fmaxf(-0.5f*gw, -0.5f*aw);
                float ch = fminf(0.5f*gh, 0.5f*ah) - fmaxf(-0.5f*gh, -0.5f*ah);
                float ca = (cw <= 0.f || ch <= 0.f) ? 0.f : cw*ch;
                float iou = ca / (gw*gh + aw*ah - ca);
                if (iou > best) { best = iou; bn = a; }
            }
            int gi = (int)floorf(gx), gj = (int)floorf(gy);
            int cell = bn*HW + gj*NW + gi;
            int cc_i = (int)cc; if (cc_i < 0) cc_i = 0; if (cc_i > NC-1) cc_i = NC-1;
            sH[tid]   = make_float4(3.f*(gx - 0.5f*gw), 3.f*(gx + 0.5f*gw),
                                    gy - 0.5f*gh, gy + 0.5f*gh);
            ((float*)sNga4)[tid] = -(gw*gh);
            sC[tid]   = make_float4(gx - (float)gi, gy - (float)gj,
                                    logf(gw / c_AW[bn]), logf(gh / c_AH[bn]));
            sD[tid]   = make_float2(sqrtf(2.f - w*h), __int_as_float(cc_i));
            sCell[tid] = cell;
            int c = cell - base;
            if (c >= 0 && c < CPB) atomicMax(&s_last[c], tid);
        } else {
            sH[tid]   = make_float4(1e38f, -1e38f, 1e38f, -1e38f);
            ((float*)sNga4)[tid] = -1e30f;
            if (tid < MAXB) {
                sC[tid]   = make_float4(0.f, 0.f, 0.f, 0.f);
                sD[tid]   = make_float2(0.f, __int_as_float(0));
                sCell[tid] = -1;
            }
        }
    }
    __syncthreads();

    // ---- per-cell prologue (consume prefetched values) ----
    float s0a, s1a, paa, px1a, px2a, py1a, py2a;
    {
        float u0 = pexp(-L00), u1 = pexp(-L01);
        float d0 = 1.f + u0, d1 = 1.f + u1;
        float rr = __fdividef(1.f, d0*d1);          // single MUFU.RCP
        s0a = d1*rr; s1a = d0*rr;
        int hh = hw0 / NW, ww = hw0 - hh*NW;
        int aq = (b*3 + a0) >> 5;                   // faithful anchor-flatten quirk
        float pw = pexp(L02)*c_AW[aq], ph = pexp(L03)*c_AH[aq];
        float px = s0a + (float)ww, py = s1a + (float)hh;
        px1a = 3.f*(px - 0.5f*pw); px2a = 3.f*(px + 0.5f*pw);
        py1a = py - 0.5f*ph;       py2a = py + 0.5f*ph;
        paa = pw*ph;
    }
    float s0b, s1b, pab, px1b, px2b, py1b, py2b;
    {
        float u0 = pexp(-L10), u1 = pexp(-L11);
        float d0 = 1.f + u0, d1 = 1.f + u1;
        float rr = __fdividef(1.f, d0*d1);
        s0b = d1*rr; s1b = d0*rr;
        int hh = hw1 / NW, ww = hw1 - hh*NW;
        int aq = (b*3 + a1) >> 5;
        float pw = pexp(L12)*c_AW[aq], ph = pexp(L13)*c_AH[aq];
        float px = s0b + (float)ww, py = s1b + (float)hh;
        px1b = 3.f*(px - 0.5f*pw); px2b = 3.f*(px + 0.5f*pw);
        py1b = py - 0.5f*ph;       py2b = py + 0.5f*ph;
        pab = pw*ph;
    }

    // ---- hot loop: 13 groups x 4 gts, branch-free ----
    float dmax0 = -1e30f, dmax1 = -1e30f;
#pragma unroll
    for (int g4 = 0; g4 < GTPAD/4; g4++) {
        float4 nga4 = sNga4[g4];
#pragma unroll
        for (int j = 0; j < 4; j++) {
            float4 A  = sH[g4*4 + j];
            float nga = (j == 0) ? nga4.x : (j == 1) ? nga4.y : (j == 2) ? nga4.z : nga4.w;
            {
                float cw = fmaxf(fminf(px2a, A.y) - fmaxf(px1a, A.x), 0.f);
                float ch = fmaxf(fminf(py2a, A.w) - fmaxf(py1a, A.z), 0.f);
                dmax0 = fmaxf(dmax0, fmaf(cw, ch, nga));   // 3*ca - ga
            }
            {
                float cw = fmaxf(fminf(px2b, A.y) - fmaxf(px1b, A.x), 0.f);
                float ch = fmaxf(fminf(py2b, A.w) - fmaxf(py1b, A.z), 0.f);
                dmax1 = fmaxf(dmax1, fmaf(cw, ch, nga));
            }
        }
    }
    bool ign0 = dmax0 > paa;       // 3*ca > pa + ga  <=>  iou > 0.5
    bool ign1 = dmax1 > pab;
    int last0 = s_last[tid];
    int last1 = s_last[tid + BLK];

    // ---- deterministic compaction of object cells into shared queue ----
    unsigned m0 = __ballot_sync(0xffffffffu, last0 >= 0);
    unsigned m1 = __ballot_sync(0xffffffffu, last1 >= 0);
    if (lane == 0) s_wcnt[wid] = __popc(m0) + __popc(m1);
    __syncthreads();
    if (tid == 0) {
        int acc = 0;
#pragma unroll
        for (int j = 0; j < NWARPS; j++) { s_wbase[j] = acc; acc += s_wcnt[j]; }
        s_qn = acc;
    }
    __syncthreads();

    float coordL = 0.f, confL = 0.f, clsL = 0.f;
    unsigned ltm = (1u << lane) - 1u;

    // conf loss: merged-log.  obj: log(1+e^-c4);  back: c4 + log(1+e^-c4);  ign: 0
    {
        bool inc0 = v0 && (last0 >= 0 || !ign0);
        bool inc1 = v1 && (last1 >= 0 || !ign1);
        float t0 = inc0 ? (1.f + pexp(-L04)) : 1.f;
        float t1 = inc1 ? (1.f + pexp(-L14)) : 1.f;
        if (inc0 && last0 < 0) confL += L04;
        if (inc1 && last1 < 0) confL += L14;
        confL += __logf(t0 * t1);
    }

    if (last0 >= 0) {
        float4 tc = sC[last0]; float m = sD[last0].x;
        float d0 = s0a*m - tc.x*m, d1 = s1a*m - tc.y*m;
        float d2 = L02*m - tc.z*m, d3 = L03*m - tc.w*m;
        coordL += 0.5f*(d0*d0 + d1*d1 + d2*d2 + d3*d3);
        unsigned cb0=0u, cb1=0u, cb2=0u;
        for (int t2 = 0; t2 < MAXB; t2++) {
            if (sCell[t2] == idx0) {
                int c = __float_as_int(sD[t2].y);
                if (c < 32)      cb0 |= 1u << c;
                else if (c < 64) cb1 |= 1u << (c - 32);
                else             cb2 |= 1u << (c - 64);
            }
        }
        int q = s_wbase[wid] + __popc(m0 & ltm);
        s_qoff[q] = off0; s_qb0[q] = cb0; s_qb1[q] = cb1; s_qb2[q] = cb2;
    }
    if (last1 >= 0) {
        float4 tc = sC[last1]; float m = sD[last1].x;
        float d0 = s0b*m - tc.x*m, d1 = s1b*m - tc.y*m;
        float d2 = L12*m - tc.z*m, d3 = L13*m - tc.w*m;
        coordL += 0.5f*(d0*d0 + d1*d1 + d2*d2 + d3*d3);
        unsigned cb0=0u, cb1=0u, cb2=0u;
        for (int t2 = 0; t2 < MAXB; t2++) {
            if (sCell[t2] == idx1) {
                int c = __float_as_int(sD[t2].y);
                if (c < 32)      cb0 |= 1u << c;
                else if (c < 64) cb1 |= 1u << (c - 32);
                else             cb2 |= 1u << (c - 64);
            }
        }
        int q = s_wbase[wid] + __popc(m0) + __popc(m1 & ltm);
        s_qoff[q] = off1; s_qb0[q] = cb0; s_qb1[q] = cb1; s_qb2[q] = cb2;
    }
    __syncthreads();

    // ---- warp-cooperative class loss: 80 classes over 32 lanes, merged log ----
    int qn = s_qn;
    for (int e = wid; e < qn; e += NWARPS) {
        int basec = s_qoff[e] + 5*HW;
        unsigned cb0 = s_qb0[e], cb1 = s_qb1[e], cb2 = s_qb2[e];
        int c0i = lane, c1i = lane + 32, c2i = lane + 64;
        bool has2 = (c2i < NC);
        float xv0 = __ldg(out + basec + c0i*HW);
        float xv1 = __ldg(out + basec + c1i*HW);
        float xv2 = has2 ? __ldg(out + basec + c2i*HW) : 0.f;
        float t0 = 1.f + pexp(-xv0);
        float t1 = 1.f + pexp(-xv1);
        float t2 = has2 ? (1.f + pexp(-xv2)) : 1.f;
        clsL += __logf(t0 * t1 * t2);               // merged: one LG2 per 3 classes
        if (!((cb0 >> c0i) & 1u)) clsL += xv0;
        if (!((cb1 >> (c1i - 32)) & 1u)) clsL += xv1;
        if (has2 && !((cb2 >> (c2i - 64)) & 1u)) clsL += xv2;
    }

    // ---- block reduce 3 sums ----
    unsigned fm = 0xffffffffu;
#pragma unroll
    for (int off = 16; off; off >>= 1) {
        coordL += __shfl_down_sync(fm, coordL, off);
        confL  += __shfl_down_sync(fm, confL,  off);
        clsL   += __shfl_down_sync(fm, clsL,   off);
    }
    if (lane == 0) { s_red[0][wid] = coordL; s_red[1][wid] = confL; s_red[2][wid] = clsL; }
    __syncthreads();
    if (tid < 3) {
        float s = 0.f;
#pragma unroll
        for (int j = 0; j < NWARPS; j++) s += s_red[tid][j];
        g_partial[blockIdx.y*gridDim.x + blockIdx.x][tid] = s;
    }
    __threadfence();
    if (tid == 0) {
        int t = atomicAdd(&g_count, 1);
        s_islast = (t == NPART - 1) ? 1 : 0;
    }
    __syncthreads();

    // ---- last block: deterministic final reduce ----
    if (s_islast) {
        volatile float* gp = &g_partial[0][0];
        float a0r = 0.f, a1r = 0.f, a2r = 0.f;
        for (int i = tid; i < NPART; i += BLK) {
            a0r += gp[i*3 + 0]; a1r += gp[i*3 + 1]; a2r += gp[i*3 + 2];
        }
#pragma unroll
        for (int off = 16; off; off >>= 1) {
            a0r += __shfl_down_sync(fm, a0r, off);
            a1r += __shfl_down_sync(fm, a1r, off);
            a2r += __shfl_down_sync(fm, a2r, off);
        }
        __shared__ float s_fin[3][NWARPS];
        if (lane == 0) { s_fin[0][wid] = a0r; s_fin[1][wid] = a1r; s_fin[2][wid] = a2r; }
        __syncthreads();
        if (tid < 3) {
            float s = 0.f;
#pragma unroll
            for (int j = 0; j < NWARPS; j++) s += s_fin[tid][j];
            dout[tid] = s / (float)NB;
        }
        if (tid == 0) g_count = 0;     // reset for next graph replay
    }
}

extern "C" void kernel_launch(void* const* d_in, const int* in_sizes, int n_in,
                              void* d_out, int out_size) {
    const float* output = (const float*)d_in[0];
    const float* target = (const float*)d_in[1];
    if (n_in >= 2 && in_sizes[0] == NB*MAXB*5) {  // defensive: inputs swapped
        output = (const float*)d_in[1];
        target = (const float*)d_in[0];
    }
    dim3 g(GXB, NB);
    kF<<<g, BLK>>>(output, target, (float*)d_out);
}

// round 10
// speedup vs baseline: 3.2248x; 1.3043x over previous
#include <cuda_runtime.h>

#define NB 32
#define NA 3
#define NH 52
#define NW 52
#define NC 80
#define HW (NH*NW)                    // 2704
#define CELLS_PER_B (NA*HW)           // 8112
#define MAXB 50
#define GTPAD 52
#define CANDMAX 56                    // 50 + 4 sentinels + pad
#define BLK 256
#define NWARPS (BLK/32)
#define CPT 2
#define CPB (BLK*CPT)                 // 512
#define GXB ((CELLS_PER_B + CPB - 1)/CPB)  // 16
#define NPART (GXB*NB)                // 512
#define QMAX 64

__constant__ float c_AW[3] = {10.f/32.f, 16.f/32.f, 33.f/32.f};
__constant__ float c_AH[3] = {13.f/32.f, 30.f/32.f, 23.f/32.f};

__device__ float g_partial[NPART][3];
__device__ int   g_count = 0;

// FMA-pipe exp: magic-number round-to-nearest + deg-6 Taylor for 2^f, exponent splice.
__device__ __forceinline__ float pexp(float x) {
    float y = x * 1.4426950408889634f;
    y = fminf(fmaxf(y, -80.f), 80.f);
    float fm = y + 12582912.f;                    // 1.5*2^23
    int   i  = __float_as_int(fm) - 0x4B400000;
    float r  = fm - 12582912.f;
    float f  = y - r;                             // f in [-0.5, 0.5]
    float p  =          1.54035304e-4f;
    p = p*f + 1.33335581e-3f;
    p = p*f + 9.61812911e-3f;
    p = p*f + 5.55041087e-2f;
    p = p*f + 2.40226507e-1f;
    p = p*f + 6.93147182e-1f;
    p = p*f + 1.f;                                // 2^f
    return __int_as_float(__float_as_int(p) + (i << 23));
}

// ---------------- fully fused kernel ----------------
__global__ void __launch_bounds__(BLK) kF(const float* __restrict__ out,
                                          const float* __restrict__ target,
                                          float* __restrict__ dout) {
    __shared__ float4   sH[GTPAD];    // {3*x1, 3*x2, y1, y2} (x pre-scaled by 3)
    __shared__ float    sNga[GTPAD];  // -garea
    __shared__ float4   sC[MAXB];     // {tx, ty, tw, th}
    __shared__ float2   sD[MAXB];     // {scale, cls-as-int}
    __shared__ int      sCell[MAXB];  // target cell (-1 invalid)
    __shared__ int      s_last[CPB];  // last gt slot targeting each local cell
    __shared__ unsigned s_bal[2];
    __shared__ float    s_pm[NWARPS];
    __shared__ float4   sHc[CANDMAX]; // compacted candidate corners
    __shared__ float    sNgac[CANDMAX];
    __shared__ int      s_nc4;
    __shared__ float    s_red[3][NWARPS];
    __shared__ int      s_wcnt[NWARPS], s_wbase[NWARPS], s_qn;
    __shared__ int      s_qoff[QMAX];
    __shared__ unsigned s_qb0[QMAX], s_qb1[QMAX], s_qb2[QMAX];
    __shared__ int      s_islast;

    int b = blockIdx.y, tid = threadIdx.x;
    int lane = tid & 31, wid = tid >> 5;
    int base = blockIdx.x*CPB;
    unsigned ltm = (1u << lane) - 1u;

    // ---- PREFETCH: issue all 10 channel loads first ----
    int idx0 = base + tid;
    int idx1 = idx0 + BLK;
    bool v0 = idx0 < CELLS_PER_B;
    bool v1 = idx1 < CELLS_PER_B;
    int i0 = v0 ? idx0 : 0;
    int i1 = v1 ? idx1 : 0;
    int a0 = i0 / HW, hw0 = i0 - a0*HW;
    int a1 = i1 / HW, hw1 = i1 - a1*HW;
    int off0 = (b*255 + a0*85)*HW + hw0;
    int off1 = (b*255 + a1*85)*HW + hw1;
    const float* o0 = out + off0;
    const float* o1 = out + off1;
    float L00 = __ldg(o0 + 0*HW), L01 = __ldg(o0 + 1*HW), L02 = __ldg(o0 + 2*HW),
          L03 = __ldg(o0 + 3*HW), L04 = __ldg(o0 + 4*HW);
    float L10 = __ldg(o1 + 0*HW), L11 = __ldg(o1 + 1*HW), L12 = __ldg(o1 + 2*HW),
          L13 = __ldg(o1 + 3*HW), L14 = __ldg(o1 + 4*HW);

    // ---- phase 1: read targets, ballot validity, init s_last ----
    bool  ok = false;
    float cc = 0.f, x = 0.f, y = 0.f, w = 0.f, h = 0.f;
    if (tid < MAXB) {
        const float* tp = target + b*MAXB*5 + tid*5;
        cc = tp[0]; x = tp[1]; y = tp[2]; w = tp[3]; h = tp[4];
        ok = (x != 0.f);
    }
    if (tid < 64) {
        unsigned bal = __ballot_sync(0xffffffffu, ok);
        if (lane == 0) s_bal[wid] = bal;
    }
    s_last[tid] = -1;
    s_last[tid + BLK] = -1;
    __syncthreads();

    // ---- phase 2: build gt table + scatter cell ownership ----
    if (tid < GTPAD) {
        bool valid = false;
        if (tid < MAXB) {
            if (tid < 32) {
                unsigned low = (tid == 31) ? 0xffffffffu : ((1u << (tid + 1)) - 1u);
                valid = ((s_bal[0] & low) == low);
            } else {
                unsigned low = (1u << (tid - 31)) - 1u;
                valid = (s_bal[0] == 0xffffffffu) && ((s_bal[1] & low) == low);
            }
        }
        if (valid) {
            float gx = x*(float)NW, gy = y*(float)NH;
            float gw = w*(float)NW, gh = h*(float)NH;
            int bn = 0; float best = -1e30f;
#pragma unroll
            for (int a = 0; a < 3; a++) {
                float aw = c_AW[a], ah = c_AH[a];
                float cw = fminf(0.5f*gw, 0.5f*aw) - fmaxf(-0.5f*gw, -0.5f*aw);
                float ch = fminf(0.5f*gh, 0.5f*ah) - fmaxf(-0.5f*gh, -0.5f*ah);
                float ca = (cw <= 0.f || ch <= 0.f) ? 0.f : cw*ch;
                float iou = ca / (gw*gh + aw*ah - ca);
                if (iou > best) { best = iou; bn = a; }
            }
            int gi = (int)floorf(gx), gj = (int)floorf(gy);
            int cell = bn*HW + gj*NW + gi;
            int cc_i = (int)cc; if (cc_i < 0) cc_i = 0; if (cc_i > NC-1) cc_i = NC-1;
            sH[tid]   = make_float4(3.f*(gx - 0.5f*gw), 3.f*(gx + 0.5f*gw),
                                    gy - 0.5f*gh, gy + 0.5f*gh);
            sNga[tid] = -(gw*gh);
            sC[tid]   = make_float4(gx - (float)gi, gy - (float)gj,
                                    logf(gw / c_AW[bn]), logf(gh / c_AH[bn]));
            sD[tid]   = make_float2(sqrtf(2.f - w*h), __int_as_float(cc_i));
            sCell[tid] = cell;
            int c = cell - base;
            if (c >= 0 && c < CPB) atomicMax(&s_last[c], tid);
        } else {
            sH[tid]   = make_float4(1e38f, -1e38f, 1e38f, -1e38f);
            sNga[tid] = -1e30f;                   // ga = +1e30 -> never passes prune
            if (tid < MAXB) {
                sC[tid]   = make_float4(0.f, 0.f, 0.f, 0.f);
                sD[tid]   = make_float2(0.f, __int_as_float(0));
                sCell[tid] = -1;
            }
        }
    }

    // ---- per-cell prologue (prefetched regs only; no shared reads) ----
    float s0a, s1a, paa, px1a, px2a, py1a, py2a;
    {
        float u0 = pexp(-L00), u1 = pexp(-L01);
        float d0 = 1.f + u0, d1 = 1.f + u1;
        float rr = __fdividef(1.f, d0*d1);          // single MUFU.RCP
        s0a = d1*rr; s1a = d0*rr;
        int hh = hw0 / NW, ww = hw0 - hh*NW;
        int aq = (b*3 + a0) >> 5;                   // faithful anchor-flatten quirk
        float pw = pexp(L02)*c_AW[aq], ph = pexp(L03)*c_AH[aq];
        float px = s0a + (float)ww, py = s1a + (float)hh;
        px1a = 3.f*(px - 0.5f*pw); px2a = 3.f*(px + 0.5f*pw);
        py1a = py - 0.5f*ph;       py2a = py + 0.5f*ph;
        paa = pw*ph;
    }
    float s0b, s1b, pab, px1b, px2b, py1b, py2b;
    {
        float u0 = pexp(-L10), u1 = pexp(-L11);
        float d0 = 1.f + u0, d1 = 1.f + u1;
        float rr = __fdividef(1.f, d0*d1);
        s0b = d1*rr; s1b = d0*rr;
        int hh = hw1 / NW, ww = hw1 - hh*NW;
        int aq = (b*3 + a1) >> 5;
        float pw = pexp(L12)*c_AW[aq], ph = pexp(L13)*c_AH[aq];
        float px = s0b + (float)ww, py = s1b + (float)hh;
        px1b = 3.f*(px - 0.5f*pw); px2b = 3.f*(px + 0.5f*pw);
        py1b = py - 0.5f*ph;       py2b = py + 0.5f*ph;
        pab = pw*ph;
    }

    // ---- block max of pred-box area (prune threshold) ----
    {
        float pm = fmaxf(v0 ? paa : 0.f, v1 ? pab : 0.f);
#pragma unroll
        for (int off = 16; off; off >>= 1)
            pm = fmaxf(pm, __shfl_xor_sync(0xffffffffu, pm, off));
        if (lane == 0) s_pm[wid] = pm;
    }
    __syncthreads();   // covers phase-2 shared writes + s_pm

    // ---- warp 0: compact candidate gts (ga < 2*pa_max is necessary for ignore) ----
    if (wid == 0) {
        float pamax = 0.f;
#pragma unroll
        for (int j = 0; j < NWARPS; j++) pamax = fmaxf(pamax, s_pm[j]);
        float th = 2.f * pamax;
        float ng0 = sNga[lane];                      // slots 0..31
        bool  c0  = (-ng0) < th;
        bool  in1 = (lane + 32) < MAXB;              // slots 32..49
        float ng1 = in1 ? sNga[lane + 32] : -1e30f;
        bool  c1  = in1 && ((-ng1) < th);
        unsigned b0 = __ballot_sync(0xffffffffu, c0);
        unsigned b1 = __ballot_sync(0xffffffffu, c1);
        int n = __popc(b0) + __popc(b1);
        if (c0) { int p = __popc(b0 & ltm);              sHc[p] = sH[lane];      sNgac[p] = ng0; }
        if (c1) { int p = __popc(b0) + __popc(b1 & ltm); sHc[p] = sH[lane + 32]; sNgac[p] = ng1; }
        if (lane < 4) {                               // sentinel pad to next mult of 4
            sHc[n + lane]   = make_float4(1e38f, -1e38f, 1e38f, -1e38f);
            sNgac[n + lane] = -1e30f;
        }
        if (lane == 0) s_nc4 = (n + 3) >> 2;
    }
    __syncthreads();

    // ---- hot loop over compacted candidates only ----
    float dmax0 = -1e30f, dmax1 = -1e30f;
    int nc4 = s_nc4;
    for (int g4 = 0; g4 < nc4; g4++) {
#pragma unroll
        for (int j = 0; j < 4; j++) {
            float4 A  = sHc[g4*4 + j];
            float nga = sNgac[g4*4 + j];
            {
                float cw = fmaxf(fminf(px2a, A.y) - fmaxf(px1a, A.x), 0.f);
                float ch = fmaxf(fminf(py2a, A.w) - fmaxf(py1a, A.z), 0.f);
                dmax0 = fmaxf(dmax0, fmaf(cw, ch, nga));   // 3*ca - ga
            }
            {
                float cw = fmaxf(fminf(px2b, A.y) - fmaxf(px1b, A.x), 0.f);
                float ch = fmaxf(fminf(py2b, A.w) - fmaxf(py1b, A.z), 0.f);
                dmax1 = fmaxf(dmax1, fmaf(cw, ch, nga));
            }
        }
    }
    bool ign0 = dmax0 > paa;       // 3*ca > pa + ga  <=>  iou > 0.5
    bool ign1 = dmax1 > pab;
    int last0 = s_last[tid];
    int last1 = s_last[tid + BLK];

    // ---- deterministic compaction of object cells into shared queue ----
    unsigned m0 = __ballot_sync(0xffffffffu, last0 >= 0);
    unsigned m1 = __ballot_sync(0xffffffffu, last1 >= 0);
    if (lane == 0) s_wcnt[wid] = __popc(m0) + __popc(m1);
    __syncthreads();
    if (tid == 0) {
        int acc = 0;
#pragma unroll
        for (int j = 0; j < NWARPS; j++) { s_wbase[j] = acc; acc += s_wcnt[j]; }
        s_qn = acc;
    }
    __syncthreads();

    float coordL = 0.f, confL = 0.f, clsL = 0.f;

    // conf loss: merged-log.  obj: log(1+e^-c4);  back: c4 + log(1+e^-c4);  ign: 0
    {
        bool inc0 = v0 && (last0 >= 0 || !ign0);
        bool inc1 = v1 && (last1 >= 0 || !ign1);
        float t0 = inc0 ? (1.f + pexp(-L04)) : 1.f;
        float t1 = inc1 ? (1.f + pexp(-L14)) : 1.f;
        if (inc0 && last0 < 0) confL += L04;
        if (inc1 && last1 < 0) confL += L14;
        confL += __logf(t0 * t1);
    }

    if (last0 >= 0) {
        float4 tc = sC[last0]; float m = sD[last0].x;
        float d0 = s0a*m - tc.x*m, d1 = s1a*m - tc.y*m;
        float d2 = L02*m - tc.z*m, d3 = L03*m - tc.w*m;
        coordL += 0.5f*(d0*d0 + d1*d1 + d2*d2 + d3*d3);
        unsigned cb0=0u, cb1=0u, cb2=0u;
        for (int t2 = 0; t2 < MAXB; t2++) {
            if (sCell[t2] == idx0) {
                int c = __float_as_int(sD[t2].y);
                if (c < 32)      cb0 |= 1u << c;
                else if (c < 64) cb1 |= 1u << (c - 32);
                else             cb2 |= 1u << (c - 64);
            }
        }
        int q = s_wbase[wid] + __popc(m0 & ltm);
        s_qoff[q] = off0; s_qb0[q] = cb0; s_qb1[q] = cb1; s_qb2[q] = cb2;
    }
    if (last1 >= 0) {
        float4 tc = sC[last1]; float m = sD[last1].x;
        float d0 = s0b*m - tc.x*m, d1 = s1b*m - tc.y*m;
        float d2 = L12*m - tc.z*m, d3 = L13*m - tc.w*m;
        coordL += 0.5f*(d0*d0 + d1*d1 + d2*d2 + d3*d3);
        unsigned cb0=0u, cb1=0u, cb2=0u;
        for (int t2 = 0; t2 < MAXB; t2++) {
            if (sCell[t2] == idx1) {
                int c = __float_as_int(sD[t2].y);
                if (c < 32)      cb0 |= 1u << c;
                else if (c < 64) cb1 |= 1u << (c - 32);
                else             cb2 |= 1u << (c - 64);
            }
        }
        int q = s_wbase[wid] + __popc(m0) + __popc(m1 & ltm);
        s_qoff[q] = off1; s_qb0[q] = cb0; s_qb1[q] = cb1; s_qb2[q] = cb2;
    }
    __syncthreads();

    // ---- warp-cooperative class loss: 80 classes over 32 lanes, merged log ----
    int qn = s_qn;
    for (int e = wid; e < qn; e += NWARPS) {
        int basec = s_qoff[e] + 5*HW;
        unsigned cb0 = s_qb0[e], cb1 = s_qb1[e], cb2 = s_qb2[e];
        int c0i = lane, c1i = lane + 32, c2i = lane + 64;
        bool has2 = (c2i < NC);
        float xv0 = __ldg(out + basec + c0i*HW);
        float xv1 = __ldg(out + basec + c1i*HW);
        float xv2 = has2 ? __ldg(out + basec + c2i*HW) : 0.f;
        float t0 = 1.f + pexp(-xv0);
        float t1 = 1.f + pexp(-xv1);
        float t2 = has2 ? (1.f + pexp(-xv2)) : 1.f;
        clsL += __logf(t0 * t1 * t2);               // merged: one LG2 per 3 classes
        if (!((cb0 >> c0i) & 1u)) clsL += xv0;
        if (!((cb1 >> (c1i - 32)) & 1u)) clsL += xv1;
        if (has2 && !((cb2 >> (c2i - 64)) & 1u)) clsL += xv2;
    }

    // ---- block reduce 3 sums ----
    unsigned fm = 0xffffffffu;
#pragma unroll
    for (int off = 16; off; off >>= 1) {
        coordL += __shfl_down_sync(fm, coordL, off);
        confL  += __shfl_down_sync(fm, confL,  off);
        clsL   += __shfl_down_sync(fm, clsL,   off);
    }
    if (lane == 0) { s_red[0][wid] = coordL; s_red[1][wid] = confL; s_red[2][wid] = clsL; }
    __syncthreads();
    if (tid < 3) {
        float s = 0.f;
#pragma unroll
        for (int j = 0; j < NWARPS; j++) s += s_red[tid][j];
        g_partial[blockIdx.y*gridDim.x + blockIdx.x][tid] = s;
    }
    __threadfence();
    if (tid == 0) {
        int t = atomicAdd(&g_count, 1);
        s_islast = (t == NPART - 1) ? 1 : 0;
    }
    __syncthreads();

    // ---- last block: deterministic final reduce ----
    if (s_islast) {
        volatile float* gp = &g_partial[0][0];
        float a0r = 0.f, a1r = 0.f, a2r = 0.f;
        for (int i = tid; i < NPART; i += BLK) {
            a0r += gp[i*3 + 0]; a1r += gp[i*3 + 1]; a2r += gp[i*3 + 2];
        }
#pragma unroll
        for (int off = 16; off; off >>= 1) {
            a0r += __shfl_down_sync(fm, a0r, off);
            a1r += __shfl_down_sync(fm, a1r, off);
            a2r += __shfl_down_sync(fm, a2r, off);
        }
        __shared__ float s_fin[3][NWARPS];
        if (lane == 0) { s_fin[0][wid] = a0r; s_fin[1][wid] = a1r; s_fin[2][wid] = a2r; }
        __syncthreads();
        if (tid < 3) {
            float s = 0.f;
#pragma unroll
            for (int j = 0; j < NWARPS; j++) s += s_fin[tid][j];
            dout[tid] = s / (float)NB;
        }
        if (tid == 0) g_count = 0;     // reset for next graph replay
    }
}

extern "C" void kernel_launch(void* const* d_in, const int* in_sizes, int n_in,
                              void* d_out, int out_size) {
    const float* output = (const float*)d_in[0];
    const float* target = (const float*)d_in[1];
    if (n_in >= 2 && in_sizes[0] == NB*MAXB*5) {  // defensive: inputs swapped
        output = (const float*)d_in[1];
        target = (const float*)d_in[0];
    }
    dim3 g(GXB, NB);
    kF<<<g, BLK>>>(output, target, (float*)d_out);
}